// round 12
// baseline (speedup 1.0000x reference)
#include <cuda_runtime.h>
#include <cuda_bf16.h>
#include <cstdint>
#include <math.h>

#define NN    100000
#define HID   128
#define FEATK 256
#define NCLS  40
#define NE    1600000
#define MAXD  64
#define PADK  72

typedef unsigned long long ull;

#define FMA_F32X2(d, a, b, c) \
    asm("fma.rn.f32x2 %0, %1, %2, %3;" : "=l"(d) : "l"(a), "l"(b), "l"(c))
#define PACK2(out, x) \
    asm("mov.b64 %0, {%1, %1};" : "=l"(out) : "r"(x))

__device__ __forceinline__ uint32_t smem_u32(const void* p) {
    uint32_t a;
    asm("{ .reg .u64 t; cvta.to.shared.u64 t, %1; cvt.u32.u64 %0, t; }"
        : "=r"(a) : "l"(p));
    return a;
}

#define LDMATRIX_X4(a0, a1, a2, a3, addr) \
    asm volatile("ldmatrix.sync.aligned.m8n8.x4.shared.b16 {%0,%1,%2,%3}, [%4];" \
        : "=r"(a0), "=r"(a1), "=r"(a2), "=r"(a3) : "r"(addr))
#define LDMATRIX_X2(b0, b1, addr) \
    asm volatile("ldmatrix.sync.aligned.m8n8.x2.shared.b16 {%0,%1}, [%2];" \
        : "=r"(b0), "=r"(b1) : "r"(addr))
#define MMA_BF16(c0, c1, c2, c3, a0, a1, a2, a3, b0, b1) \
    asm volatile("mma.sync.aligned.m16n8k16.row.col.f32.bf16.bf16.f32 " \
        "{%0,%1,%2,%3}, {%4,%5,%6,%7}, {%8,%9}, {%0,%1,%2,%3};" \
        : "+f"(c0), "+f"(c1), "+f"(c2), "+f"(c3) \
        : "r"(a0), "r"(a1), "r"(a2), "r"(a3), "r"(b0), "r"(b1))

__device__ __forceinline__ void f2bf_split(float x, __nv_bfloat16& h, __nv_bfloat16& l) {
    h = __float2bfloat16_rn(x);
    l = __float2bfloat16_rn(x - __bfloat162float(h));
}

// ---- scratch ----
__device__ float g_agg[(size_t)NN * HID];
__device__ float g_out2[(size_t)NN * NCLS];
__device__ float g_U[2 * HID * NCLS];
__device__ float g_c[NCLS];
__device__ int g_cnt[NN];
__device__ int g_buf2[(size_t)NN * MAXD];
__device__ __nv_bfloat16 g_W1T_hi[HID * FEATK];
__device__ __nv_bfloat16 g_W1T_lo[HID * FEATK];
__device__ __nv_bfloat16 g_W2T_hi[HID * HID];
__device__ __nv_bfloat16 g_W2T_lo[HID * HID];

// ---------------------------------------------------------------------------
__global__ void zero_cnt_kernel() {
    int i = blockIdx.x * blockDim.x + threadIdx.x;
    if (i < NN) g_cnt[i] = 0;
}

// ---------------------------------------------------------------------------
__global__ void convw_kernel(const float* __restrict__ W1, const float* __restrict__ W2) {
    int i = blockIdx.x * 256 + threadIdx.x;
    if (i < HID * FEATK) {
        int n = i / FEATK, k = i % FEATK;
        __nv_bfloat16 h, l;
        f2bf_split(W1[(size_t)k * HID + n], h, l);
        g_W1T_hi[i] = h; g_W1T_lo[i] = l;
    } else {
        int j = i - HID * FEATK;
        if (j < HID * HID) {
            int n = j / HID, k = j % HID;
            __nv_bfloat16 h, l;
            f2bf_split(W2[(size_t)k * HID + n], h, l);
            g_W2T_hi[j] = h; g_W2T_lo[j] = l;
        }
    }
}

// ---------------------------------------------------------------------------
__global__ void prep_kernel(const float* __restrict__ Ww, const float* __restrict__ Wo,
                            const float* __restrict__ bw, const float* __restrict__ bo) {
    int t = blockIdx.x * 256 + threadIdx.x;
    int i = t / NCLS;
    int j = t % NCLS;
    float s = 0.f;
#pragma unroll 8
    for (int k = 0; k < HID; k++)
        s += Ww[i * HID + k] * Wo[k * NCLS + j];
    g_U[i * NCLS + j] = s + Wo[(i & (HID - 1)) * NCLS + j];
    if (blockIdx.x == 0 && threadIdx.x < NCLS) {
        float c = 0.f;
        for (int k = 0; k < HID; k++)
            c += bw[k] * Wo[k * NCLS + threadIdx.x];
        g_c[threadIdx.x] = c + bo[threadIdx.x];
    }
}

// ---------------------------------------------------------------------------
__global__ void scatter_kernel(const int* __restrict__ ei, int E) {
    int e = blockIdx.x * blockDim.x + threadIdx.x;
    if (e >= E) return;
    int row = __ldg(&ei[e]);
    int col = __ldg(&ei[E + e]);
    int pos = atomicAdd(&g_cnt[col], 1);
    if (pos < MAXD)
        g_buf2[(size_t)col * MAXD + pos] = row;
}

// ---------------------------------------------------------------------------
__global__ void agg_kernel(const float* __restrict__ Wadj) {
    long long gid = (long long)blockIdx.x * blockDim.x + threadIdx.x;
    int n = (int)(gid >> 5);
    if (n >= NN) return;
    int lane = (int)(gid & 31);
    int craw = g_cnt[n];
    int c = min(craw, MAXD);
    const int* buf = g_buf2 + (size_t)n * MAXD;
    float4 acc = make_float4(0.f, 0.f, 0.f, 0.f);
    int i = 0;
    for (; i + 3 < c; i += 4) {
        int r0 = __ldg(&buf[i]);
        int r1 = __ldg(&buf[i + 1]);
        int r2 = __ldg(&buf[i + 2]);
        int r3 = __ldg(&buf[i + 3]);
        float4 v0 = __ldg((const float4*)(Wadj + (size_t)r0 * HID) + lane);
        float4 v1 = __ldg((const float4*)(Wadj + (size_t)r1 * HID) + lane);
        float4 v2 = __ldg((const float4*)(Wadj + (size_t)r2 * HID) + lane);
        float4 v3 = __ldg((const float4*)(Wadj + (size_t)r3 * HID) + lane);
        acc.x += (v0.x + v1.x) + (v2.x + v3.x);
        acc.y += (v0.y + v1.y) + (v2.y + v3.y);
        acc.z += (v0.z + v1.z) + (v2.z + v3.z);
        acc.w += (v0.w + v1.w) + (v2.w + v3.w);
    }
    for (; i < c; i++) {
        int r0 = __ldg(&buf[i]);
        float4 v0 = __ldg((const float4*)(Wadj + (size_t)r0 * HID) + lane);
        acc.x += v0.x; acc.y += v0.y; acc.z += v0.z; acc.w += v0.w;
    }
    float scale = 1.f + 1.f / fmaxf((float)craw, 1.f);
    acc.x *= scale; acc.y *= scale; acc.z *= scale; acc.w *= scale;
    *((float4*)(g_agg + (size_t)n * HID) + lane) = acc;
}

// ---------------------------------------------------------------------------
// out[i] += out2[i]  (4M floats)
__global__ void add_kernel(float* __restrict__ out) {
    size_t i = (size_t)blockIdx.x * blockDim.x + threadIdx.x;
    if (i < (size_t)NN * NCLS / 4) {
        float4 a = ((const float4*)out)[i];
        float4 b = ((const float4*)g_out2)[i];
        a.x += b.x; a.y += b.y; a.z += b.z; a.w += b.w;
        ((float4*)out)[i] = a;
    }
}

// ---------------------------------------------------------------------------
// Fused HMMA bf16x3 GEMM + output projection.
// H = relu(A[M,Kdim] @ B[Kdim,128] + bias)  (smem only)
// SECOND=false: out  = H @ g_U[0:128]  + g_c
// SECOND=true : out2 = H @ g_U[128:256]        (plain store, no RMW)
template <int Kdim, bool SECOND>
__global__ void __launch_bounds__(256, 2)
gemm_fused(const float* __restrict__ A,
           const __nv_bfloat16* __restrict__ BT_hi, const __nv_bfloat16* __restrict__ BT_lo,
           const float* __restrict__ bias, float* __restrict__ out, int M) {
    extern __shared__ __nv_bfloat16 sm[];
    __nv_bfloat16* As_hi = sm;
    __nv_bfloat16* As_lo = sm + 128 * PADK;
    __nv_bfloat16* Bs_hi = sm + 2 * 128 * PADK;
    __nv_bfloat16* Bs_lo = sm + 3 * 128 * PADK;
    __shared__ float Uc[64][NCLS];

    int tid = threadIdx.x;
    int wid = tid >> 5;
    int lane = tid & 31;
    int m0 = blockIdx.x * 128;
    int warp_m = wid >> 2;
    int warp_n = wid & 3;

    uint32_t uAh = smem_u32(As_hi);
    uint32_t uAl = smem_u32(As_lo);
    uint32_t uBh = smem_u32(Bs_hi);
    uint32_t uBl = smem_u32(Bs_lo);

    float acc[4][4][4];
#pragma unroll
    for (int i = 0; i < 4; i++)
#pragma unroll
        for (int j = 0; j < 4; j++)
#pragma unroll
            for (int f = 0; f < 4; f++) acc[i][j][f] = 0.f;

    int a_row = lane & 15;
    int a_col = (lane >> 4) << 3;
    int b_row = lane & 7;
    int b_col = ((lane >> 3) & 1) << 3;

    constexpr int NC = Kdim / 64;
    for (int kc = 0; kc < NC; kc++) {
        int kb = kc * 64;
        __syncthreads();
#pragma unroll
        for (int t = 0; t < 8; t++) {
            int idx4 = tid + t * 256;
            int r = idx4 >> 4;
            int c4 = (idx4 & 15) * 4;
            float4 v = make_float4(0.f, 0.f, 0.f, 0.f);
            if (m0 + r < M)
                v = *(const float4*)(A + (size_t)(m0 + r) * Kdim + kb + c4);
            __nv_bfloat16 hx, lx, hy, ly, hz, lz, hw, lw;
            f2bf_split(v.x, hx, lx); f2bf_split(v.y, hy, ly);
            f2bf_split(v.z, hz, lz); f2bf_split(v.w, hw, lw);
            __nv_bfloat162 h01 = {hx, hy}, h23 = {hz, hw};
            __nv_bfloat162 l01 = {lx, ly}, l23 = {lz, lw};
            uint2 hv = {*(uint32_t*)&h01, *(uint32_t*)&h23};
            uint2 lv = {*(uint32_t*)&l01, *(uint32_t*)&l23};
            *(uint2*)(As_hi + r * PADK + c4) = hv;
            *(uint2*)(As_lo + r * PADK + c4) = lv;
        }
#pragma unroll
        for (int t = 0; t < 4; t++) {
            int idx8 = tid + t * 256;
            int r = idx8 >> 3;
            int c8 = (idx8 & 7) * 8;
            uint4 vh = *(const uint4*)(BT_hi + (size_t)r * Kdim + kb + c8);
            uint4 vl = *(const uint4*)(BT_lo + (size_t)r * Kdim + kb + c8);
            *(uint4*)(Bs_hi + r * PADK + c8) = vh;
            *(uint4*)(Bs_lo + r * PADK + c8) = vl;
        }
        __syncthreads();

#pragma unroll
        for (int ks = 0; ks < 4; ks++) {
            int kcol = ks * 16;
            uint32_t ah[4][4], al[4][4];
#pragma unroll
            for (int mt = 0; mt < 4; mt++) {
                int row = warp_m * 64 + mt * 16 + a_row;
                uint32_t offs = (uint32_t)((row * PADK + kcol + a_col) * 2);
                LDMATRIX_X4(ah[mt][0], ah[mt][1], ah[mt][2], ah[mt][3], uAh + offs);
                LDMATRIX_X4(al[mt][0], al[mt][1], al[mt][2], al[mt][3], uAl + offs);
            }
#pragma unroll
            for (int nt = 0; nt < 4; nt++) {
                int row = warp_n * 32 + nt * 8 + b_row;
                uint32_t offs = (uint32_t)((row * PADK + kcol + b_col) * 2);
                uint32_t bh0, bh1, bl0, bl1;
                LDMATRIX_X2(bh0, bh1, uBh + offs);
                LDMATRIX_X2(bl0, bl1, uBl + offs);
#pragma unroll
                for (int mt = 0; mt < 4; mt++) {
                    float* c = acc[mt][nt];
                    MMA_BF16(c[0], c[1], c[2], c[3],
                             ah[mt][0], ah[mt][1], ah[mt][2], ah[mt][3], bh0, bh1);
                    MMA_BF16(c[0], c[1], c[2], c[3],
                             ah[mt][0], ah[mt][1], ah[mt][2], ah[mt][3], bl0, bl1);
                    MMA_BF16(c[0], c[1], c[2], c[3],
                             al[mt][0], al[mt][1], al[mt][2], al[mt][3], bh0, bh1);
                }
            }
        }
    }

    // ---- fused epilogue 1: bias+relu, store tile TRANSPOSED to smem ----
    __syncthreads();
    float* Ht = (float*)sm;          // [128 cols][129] fp32
    int cbase = warp_n * 32 + 2 * (lane & 3);
#pragma unroll
    for (int nt = 0; nt < 4; nt++) {
        int col = cbase + nt * 8;
        float b0 = bias[col], b1 = bias[col + 1];
#pragma unroll
        for (int mt = 0; mt < 4; mt++) {
            float* c = acc[mt][nt];
            int rl = warp_m * 64 + mt * 16 + (lane >> 2);
            Ht[col * 129 + rl]           = fmaxf(c[0] + b0, 0.f);
            Ht[(col + 1) * 129 + rl]     = fmaxf(c[1] + b1, 0.f);
            Ht[col * 129 + rl + 8]       = fmaxf(c[2] + b0, 0.f);
            Ht[(col + 1) * 129 + rl + 8] = fmaxf(c[3] + b1, 0.f);
        }
    }

    // ---- fused epilogue 2: out = Ht @ U_half (+ g_c) via FFMA2 ----
    int row = tid >> 1;
    int q = tid & 1;
    const int UOFS = SECOND ? (HID * NCLS) : 0;

    ull acc2[10];
#pragma unroll
    for (int j = 0; j < 10; j++) acc2[j] = 0ull;

#pragma unroll
    for (int kc2 = 0; kc2 < 2; kc2++) {
        __syncthreads();
#pragma unroll
        for (int t = 0; t < 10; t++) {
            int idx = tid + t * 256;
            Uc[idx / NCLS][idx % NCLS] = g_U[UOFS + kc2 * 64 * NCLS + idx];
        }
        __syncthreads();
#pragma unroll 4
        for (int k = 0; k < 64; k++) {
            float a = Ht[(kc2 * 64 + k) * 129 + row];
            ull a2; PACK2(a2, __float_as_uint(a));
            const ull* up = (const ull*)&Uc[k][q * 20];
#pragma unroll
            for (int j = 0; j < 10; j++)
                FMA_F32X2(acc2[j], a2, up[j], acc2[j]);
        }
    }

    int r = m0 + row;
    if (r < M) {
        float res[20];
#pragma unroll
        for (int j = 0; j < 10; j++) {
            double d = __longlong_as_double((long long)acc2[j]);
            res[2 * j]     = __uint_as_float((unsigned)__double2loint(d));
            res[2 * j + 1] = __uint_as_float((unsigned)__double2hiint(d));
        }
        float* op = out + (size_t)r * NCLS + q * 20;
        if (SECOND) {
#pragma unroll
            for (int v = 0; v < 5; v++)
                *(float4*)(op + v * 4) = *(float4*)&res[v * 4];
        } else {
#pragma unroll
            for (int v = 0; v < 5; v++) {
                float4 o;
                o.x = res[v * 4 + 0] + g_c[q * 20 + v * 4 + 0];
                o.y = res[v * 4 + 1] + g_c[q * 20 + v * 4 + 1];
                o.z = res[v * 4 + 2] + g_c[q * 20 + v * 4 + 2];
                o.w = res[v * 4 + 3] + g_c[q * 20 + v * 4 + 3];
                *(float4*)(op + v * 4) = o;
            }
        }
    }
}

// ---------------------------------------------------------------------------
extern "C" void kernel_launch(void* const* d_in, const int* in_sizes, int n_in,
                              void* d_out, int out_size) {
    const float* X    = (const float*)d_in[0];
    const int*   ei   = (const int*)d_in[1];
    const float* Wadj = (const float*)d_in[3];
    const float* W1   = (const float*)d_in[4];
    const float* b1   = (const float*)d_in[5];
    const float* W2   = (const float*)d_in[6];
    const float* b2   = (const float*)d_in[7];
    const float* Ww   = (const float*)d_in[8];
    const float* bw   = (const float*)d_in[9];
    const float* Wo   = (const float*)d_in[10];
    const float* bo   = (const float*)d_in[11];
    float* out = (float*)d_out;

    int E = in_sizes[1] / 2;
    int M = NN;

    float *pAgg, *pOut2;
    cudaGetSymbolAddress((void**)&pAgg, g_agg);
    cudaGetSymbolAddress((void**)&pOut2, g_out2);
    __nv_bfloat16 *pW1h, *pW1l, *pW2h, *pW2l;
    cudaGetSymbolAddress((void**)&pW1h, g_W1T_hi);
    cudaGetSymbolAddress((void**)&pW1l, g_W1T_lo);
    cudaGetSymbolAddress((void**)&pW2h, g_W2T_hi);
    cudaGetSymbolAddress((void**)&pW2l, g_W2T_lo);

    const int SMEM_DYN = 4 * 128 * PADK * 2;   // 73728 B
    cudaFuncSetAttribute((const void*)gemm_fused<FEATK, false>,
                         cudaFuncAttributeMaxDynamicSharedMemorySize, SMEM_DYN);
    cudaFuncSetAttribute((const void*)gemm_fused<HID, true>,
                         cudaFuncAttributeMaxDynamicSharedMemorySize, SMEM_DYN);

    int ggrid = (M + 127) / 128;
    int cgrid = (HID * FEATK + HID * HID + 255) / 256;

    // one-time host resources (no device allocation)
    static cudaStream_t s2 = nullptr;
    static cudaEvent_t evF = nullptr, evC = nullptr, evJ = nullptr;
    if (s2 == nullptr) {
        cudaStreamCreateWithFlags(&s2, cudaStreamNonBlocking);
        cudaEventCreateWithFlags(&evF, cudaEventDisableTiming);
        cudaEventCreateWithFlags(&evC, cudaEventDisableTiming);
        cudaEventCreateWithFlags(&evJ, cudaEventDisableTiming);
    }

    // fork
    cudaEventRecord(evF, 0);
    cudaStreamWaitEvent(s2, evF, 0);

    // chain A (stream 0): convw -> prep -> gemm1 (writes out)
    convw_kernel<<<cgrid, 256>>>(W1, W2);                                   // #1
    cudaEventRecord(evC, 0);    // gemm2 needs W2T
    prep_kernel<<<40, 256>>>(Ww, Wo, bw, bo);                               // #2
    // chain B (s2): zero -> scatter -> agg -> gemm2 (writes out2)
    zero_cnt_kernel<<<(NN + 255) / 256, 256, 0, s2>>>();                    // #3
    gemm_fused<FEATK, false><<<ggrid, 256, SMEM_DYN>>>(X, pW1h, pW1l, b1, out, M); // #4 <- profiled
    scatter_kernel<<<(E + 255) / 256, 256, 0, s2>>>(ei, E);                 // #5
    long long athreads = (long long)NN * 32;
    agg_kernel<<<(int)((athreads + 255) / 256), 256, 0, s2>>>(Wadj);        // #6
    cudaStreamWaitEvent(s2, evC, 0);
    gemm_fused<HID, true><<<ggrid, 256, SMEM_DYN>>>(pAgg, pW2h, pW2l, b2, pOut2, M); // #7 (concurrent with gemm1 tail)

    // join: out += out2 (needs gemm1 [stream 0 order] and gemm2 [evJ])
    cudaEventRecord(evJ, s2);
    cudaStreamWaitEvent(0, evJ, 0);
    add_kernel<<<(NN * NCLS / 4 + 255) / 256, 256>>>(out);                  // #8
}

// round 13
// speedup vs baseline: 1.0248x; 1.0248x over previous
#include <cuda_runtime.h>
#include <cuda_bf16.h>
#include <cstdint>
#include <math.h>

#define NN    100000
#define HID   128
#define FEATK 256
#define NCLS  40
#define NE    1600000
#define MAXD  64
#define PADK  72

typedef unsigned long long ull;

#define FMA_F32X2(d, a, b, c) \
    asm("fma.rn.f32x2 %0, %1, %2, %3;" : "=l"(d) : "l"(a), "l"(b), "l"(c))
#define PACK2(out, x) \
    asm("mov.b64 %0, {%1, %1};" : "=l"(out) : "r"(x))

__device__ __forceinline__ uint32_t smem_u32(const void* p) {
    uint32_t a;
    asm("{ .reg .u64 t; cvta.to.shared.u64 t, %1; cvt.u32.u64 %0, t; }"
        : "=r"(a) : "l"(p));
    return a;
}

#define LDMATRIX_X4(a0, a1, a2, a3, addr) \
    asm volatile("ldmatrix.sync.aligned.m8n8.x4.shared.b16 {%0,%1,%2,%3}, [%4];" \
        : "=r"(a0), "=r"(a1), "=r"(a2), "=r"(a3) : "r"(addr))
#define LDMATRIX_X2(b0, b1, addr) \
    asm volatile("ldmatrix.sync.aligned.m8n8.x2.shared.b16 {%0,%1}, [%2];" \
        : "=r"(b0), "=r"(b1) : "r"(addr))
#define MMA_BF16(c0, c1, c2, c3, a0, a1, a2, a3, b0, b1) \
    asm volatile("mma.sync.aligned.m16n8k16.row.col.f32.bf16.bf16.f32 " \
        "{%0,%1,%2,%3}, {%4,%5,%6,%7}, {%8,%9}, {%0,%1,%2,%3};" \
        : "+f"(c0), "+f"(c1), "+f"(c2), "+f"(c3) \
        : "r"(a0), "r"(a1), "r"(a2), "r"(a3), "r"(b0), "r"(b1))

__device__ __forceinline__ void f2bf_split(float x, __nv_bfloat16& h, __nv_bfloat16& l) {
    h = __float2bfloat16_rn(x);
    l = __float2bfloat16_rn(x - __bfloat162float(h));
}

// ---- scratch ----
__device__ float g_agg[(size_t)NN * HID];
__device__ float g_U[2 * HID * NCLS];
__device__ float g_c[NCLS];
__device__ int g_cnt[NN];
__device__ int g_buf2[(size_t)NN * MAXD];
__device__ __nv_bfloat16 g_W1T_hi[HID * FEATK];
__device__ __nv_bfloat16 g_W1T_lo[HID * FEATK];
__device__ __nv_bfloat16 g_W2T_hi[HID * HID];
__device__ __nv_bfloat16 g_W2T_lo[HID * HID];

// ---------------------------------------------------------------------------
__global__ void zero_cnt_kernel() {
    int i = blockIdx.x * blockDim.x + threadIdx.x;
    if (i < NN) g_cnt[i] = 0;
}

// ---------------------------------------------------------------------------
__global__ void convw_kernel(const float* __restrict__ W1, const float* __restrict__ W2) {
    int i = blockIdx.x * 256 + threadIdx.x;
    if (i < HID * FEATK) {
        int n = i / FEATK, k = i % FEATK;
        __nv_bfloat16 h, l;
        f2bf_split(W1[(size_t)k * HID + n], h, l);
        g_W1T_hi[i] = h; g_W1T_lo[i] = l;
    } else {
        int j = i - HID * FEATK;
        if (j < HID * HID) {
            int n = j / HID, k = j % HID;
            __nv_bfloat16 h, l;
            f2bf_split(W2[(size_t)k * HID + n], h, l);
            g_W2T_hi[j] = h; g_W2T_lo[j] = l;
        }
    }
}

// ---------------------------------------------------------------------------
__global__ void prep_kernel(const float* __restrict__ Ww, const float* __restrict__ Wo,
                            const float* __restrict__ bw, const float* __restrict__ bo) {
    int t = blockIdx.x * 256 + threadIdx.x;
    int i = t / NCLS;
    int j = t % NCLS;
    float s = 0.f;
#pragma unroll 8
    for (int k = 0; k < HID; k++)
        s += Ww[i * HID + k] * Wo[k * NCLS + j];
    g_U[i * NCLS + j] = s + Wo[(i & (HID - 1)) * NCLS + j];
    if (blockIdx.x == 0 && threadIdx.x < NCLS) {
        float c = 0.f;
        for (int k = 0; k < HID; k++)
            c += bw[k] * Wo[k * NCLS + threadIdx.x];
        g_c[threadIdx.x] = c + bo[threadIdx.x];
    }
}

// ---------------------------------------------------------------------------
__global__ void scatter_kernel(const int* __restrict__ ei, int E) {
    int e = blockIdx.x * blockDim.x + threadIdx.x;
    if (e >= E) return;
    int row = __ldg(&ei[e]);
    int col = __ldg(&ei[E + e]);
    int pos = atomicAdd(&g_cnt[col], 1);
    if (pos < MAXD)
        g_buf2[(size_t)col * MAXD + pos] = row;
}

// ---------------------------------------------------------------------------
__global__ void agg_kernel(const float* __restrict__ Wadj) {
    long long gid = (long long)blockIdx.x * blockDim.x + threadIdx.x;
    int n = (int)(gid >> 5);
    if (n >= NN) return;
    int lane = (int)(gid & 31);
    int craw = g_cnt[n];
    int c = min(craw, MAXD);
    const int* buf = g_buf2 + (size_t)n * MAXD;
    float4 acc = make_float4(0.f, 0.f, 0.f, 0.f);
    int i = 0;
    for (; i + 3 < c; i += 4) {
        int r0 = __ldg(&buf[i]);
        int r1 = __ldg(&buf[i + 1]);
        int r2 = __ldg(&buf[i + 2]);
        int r3 = __ldg(&buf[i + 3]);
        float4 v0 = __ldg((const float4*)(Wadj + (size_t)r0 * HID) + lane);
        float4 v1 = __ldg((const float4*)(Wadj + (size_t)r1 * HID) + lane);
        float4 v2 = __ldg((const float4*)(Wadj + (size_t)r2 * HID) + lane);
        float4 v3 = __ldg((const float4*)(Wadj + (size_t)r3 * HID) + lane);
        acc.x += (v0.x + v1.x) + (v2.x + v3.x);
        acc.y += (v0.y + v1.y) + (v2.y + v3.y);
        acc.z += (v0.z + v1.z) + (v2.z + v3.z);
        acc.w += (v0.w + v1.w) + (v2.w + v3.w);
    }
    for (; i < c; i++) {
        int r0 = __ldg(&buf[i]);
        float4 v0 = __ldg((const float4*)(Wadj + (size_t)r0 * HID) + lane);
        acc.x += v0.x; acc.y += v0.y; acc.z += v0.z; acc.w += v0.w;
    }
    float scale = 1.f + 1.f / fmaxf((float)craw, 1.f);
    acc.x *= scale; acc.y *= scale; acc.z *= scale; acc.w *= scale;
    *((float4*)(g_agg + (size_t)n * HID) + lane) = acc;
}

// ---------------------------------------------------------------------------
// Fused HMMA bf16x3 GEMM + output projection.
// H = relu(A[M,Kdim] @ B[Kdim,128] + bias)  (smem only)
// ADD=false: out[M,40]  = H @ g_U[0:128]  + g_c
// ADD=true : out[M,40] += H @ g_U[128:256]
template <int Kdim, bool ADD>
__global__ void __launch_bounds__(256, 2)
gemm_fused(const float* __restrict__ A,
           const __nv_bfloat16* __restrict__ BT_hi, const __nv_bfloat16* __restrict__ BT_lo,
           const float* __restrict__ bias, float* __restrict__ out, int M) {
    extern __shared__ __nv_bfloat16 sm[];
    __nv_bfloat16* As_hi = sm;
    __nv_bfloat16* As_lo = sm + 128 * PADK;
    __nv_bfloat16* Bs_hi = sm + 2 * 128 * PADK;
    __nv_bfloat16* Bs_lo = sm + 3 * 128 * PADK;
    __shared__ float Uc[HID][NCLS];   // full U half: 128x40 fp32 = 20.5 KB

    int tid = threadIdx.x;
    int wid = tid >> 5;
    int lane = tid & 31;
    int m0 = blockIdx.x * 128;
    int warp_m = wid >> 2;
    int warp_n = wid & 3;

    uint32_t uAh = smem_u32(As_hi);
    uint32_t uAl = smem_u32(As_lo);
    uint32_t uBh = smem_u32(Bs_hi);
    uint32_t uBl = smem_u32(Bs_lo);

    float acc[4][4][4];
#pragma unroll
    for (int i = 0; i < 4; i++)
#pragma unroll
        for (int j = 0; j < 4; j++)
#pragma unroll
            for (int f = 0; f < 4; f++) acc[i][j][f] = 0.f;

    int a_row = lane & 15;
    int a_col = (lane >> 4) << 3;
    int b_row = lane & 7;
    int b_col = ((lane >> 3) & 1) << 3;

    constexpr int NC = Kdim / 64;
    for (int kc = 0; kc < NC; kc++) {
        int kb = kc * 64;
        __syncthreads();
#pragma unroll
        for (int t = 0; t < 8; t++) {
            int idx4 = tid + t * 256;
            int r = idx4 >> 4;
            int c4 = (idx4 & 15) * 4;
            float4 v = make_float4(0.f, 0.f, 0.f, 0.f);
            if (m0 + r < M)
                v = *(const float4*)(A + (size_t)(m0 + r) * Kdim + kb + c4);
            __nv_bfloat16 hx, lx, hy, ly, hz, lz, hw, lw;
            f2bf_split(v.x, hx, lx); f2bf_split(v.y, hy, ly);
            f2bf_split(v.z, hz, lz); f2bf_split(v.w, hw, lw);
            __nv_bfloat162 h01 = {hx, hy}, h23 = {hz, hw};
            __nv_bfloat162 l01 = {lx, ly}, l23 = {lz, lw};
            uint2 hv = {*(uint32_t*)&h01, *(uint32_t*)&h23};
            uint2 lv = {*(uint32_t*)&l01, *(uint32_t*)&l23};
            *(uint2*)(As_hi + r * PADK + c4) = hv;
            *(uint2*)(As_lo + r * PADK + c4) = lv;
        }
#pragma unroll
        for (int t = 0; t < 4; t++) {
            int idx8 = tid + t * 256;
            int r = idx8 >> 3;
            int c8 = (idx8 & 7) * 8;
            uint4 vh = *(const uint4*)(BT_hi + (size_t)r * Kdim + kb + c8);
            uint4 vl = *(const uint4*)(BT_lo + (size_t)r * Kdim + kb + c8);
            *(uint4*)(Bs_hi + r * PADK + c8) = vh;
            *(uint4*)(Bs_lo + r * PADK + c8) = vl;
        }
        __syncthreads();

#pragma unroll
        for (int ks = 0; ks < 4; ks++) {
            int kcol = ks * 16;
            uint32_t ah[4][4], al[4][4];
#pragma unroll
            for (int mt = 0; mt < 4; mt++) {
                int row = warp_m * 64 + mt * 16 + a_row;
                uint32_t offs = (uint32_t)((row * PADK + kcol + a_col) * 2);
                LDMATRIX_X4(ah[mt][0], ah[mt][1], ah[mt][2], ah[mt][3], uAh + offs);
                LDMATRIX_X4(al[mt][0], al[mt][1], al[mt][2], al[mt][3], uAl + offs);
            }
#pragma unroll
            for (int nt = 0; nt < 4; nt++) {
                int row = warp_n * 32 + nt * 8 + b_row;
                uint32_t offs = (uint32_t)((row * PADK + kcol + b_col) * 2);
                uint32_t bh0, bh1, bl0, bl1;
                LDMATRIX_X2(bh0, bh1, uBh + offs);
                LDMATRIX_X2(bl0, bl1, uBl + offs);
#pragma unroll
                for (int mt = 0; mt < 4; mt++) {
                    float* c = acc[mt][nt];
                    MMA_BF16(c[0], c[1], c[2], c[3],
                             ah[mt][0], ah[mt][1], ah[mt][2], ah[mt][3], bh0, bh1);
                    MMA_BF16(c[0], c[1], c[2], c[3],
                             ah[mt][0], ah[mt][1], ah[mt][2], ah[mt][3], bl0, bl1);
                    MMA_BF16(c[0], c[1], c[2], c[3],
                             al[mt][0], al[mt][1], al[mt][2], al[mt][3], bh0, bh1);
                }
            }
        }
    }

    // ---- stage full U half into Uc (independent of Ht; hides under it) ----
    const int UOFS = ADD ? (HID * NCLS) : 0;
#pragma unroll
    for (int t = 0; t < 20; t++) {
        int idx = tid + t * 256;          // 5120 = 128*40
        Uc[idx / NCLS][idx % NCLS] = g_U[UOFS + idx];
    }

    // ---- epilogue 1: bias+relu, store tile TRANSPOSED to smem ----
    __syncthreads();                      // staging smem dead; reuse as Ht
    float* Ht = (float*)sm;               // [128 cols][129] fp32
    int cbase = warp_n * 32 + 2 * (lane & 3);
#pragma unroll
    for (int nt = 0; nt < 4; nt++) {
        int col = cbase + nt * 8;
        float b0 = bias[col], b1 = bias[col + 1];
#pragma unroll
        for (int mt = 0; mt < 4; mt++) {
            float* c = acc[mt][nt];
            int rl = warp_m * 64 + mt * 16 + (lane >> 2);
            Ht[col * 129 + rl]           = fmaxf(c[0] + b0, 0.f);
            Ht[(col + 1) * 129 + rl]     = fmaxf(c[1] + b1, 0.f);
            Ht[col * 129 + rl + 8]       = fmaxf(c[2] + b0, 0.f);
            Ht[(col + 1) * 129 + rl + 8] = fmaxf(c[3] + b1, 0.f);
        }
    }
    __syncthreads();

    // ---- epilogue 2: out(+)= Ht @ U_half (+ g_c) via FFMA2, sync-free ----
    int row = tid >> 1;
    int q = tid & 1;

    ull acc2[10];
#pragma unroll
    for (int j = 0; j < 10; j++) acc2[j] = 0ull;

#pragma unroll 4
    for (int k = 0; k < HID; k++) {
        float a = Ht[k * 129 + row];
        ull a2; PACK2(a2, __float_as_uint(a));
        const ull* up = (const ull*)&Uc[k][q * 20];
#pragma unroll
        for (int j = 0; j < 10; j++)
            FMA_F32X2(acc2[j], a2, up[j], acc2[j]);
    }

    int r = m0 + row;
    if (r < M) {
        float res[20];
#pragma unroll
        for (int j = 0; j < 10; j++) {
            double d = __longlong_as_double((long long)acc2[j]);
            res[2 * j]     = __uint_as_float((unsigned)__double2loint(d));
            res[2 * j + 1] = __uint_as_float((unsigned)__double2hiint(d));
        }
        float* op = out + (size_t)r * NCLS + q * 20;
        if (ADD) {
#pragma unroll
            for (int v = 0; v < 5; v++) {
                float4 o = *(float4*)(op + v * 4);
                o.x += res[v * 4 + 0]; o.y += res[v * 4 + 1];
                o.z += res[v * 4 + 2]; o.w += res[v * 4 + 3];
                *(float4*)(op + v * 4) = o;
            }
        } else {
#pragma unroll
            for (int v = 0; v < 5; v++) {
                float4 o;
                o.x = res[v * 4 + 0] + g_c[q * 20 + v * 4 + 0];
                o.y = res[v * 4 + 1] + g_c[q * 20 + v * 4 + 1];
                o.z = res[v * 4 + 2] + g_c[q * 20 + v * 4 + 2];
                o.w = res[v * 4 + 3] + g_c[q * 20 + v * 4 + 3];
                *(float4*)(op + v * 4) = o;
            }
        }
    }
}

// ---------------------------------------------------------------------------
extern "C" void kernel_launch(void* const* d_in, const int* in_sizes, int n_in,
                              void* d_out, int out_size) {
    const float* X    = (const float*)d_in[0];
    const int*   ei   = (const int*)d_in[1];
    const float* Wadj = (const float*)d_in[3];
    const float* W1   = (const float*)d_in[4];
    const float* b1   = (const float*)d_in[5];
    const float* W2   = (const float*)d_in[6];
    const float* b2   = (const float*)d_in[7];
    const float* Ww   = (const float*)d_in[8];
    const float* bw   = (const float*)d_in[9];
    const float* Wo   = (const float*)d_in[10];
    const float* bo   = (const float*)d_in[11];
    float* out = (float*)d_out;

    int E = in_sizes[1] / 2;
    int M = NN;

    float* pAgg;
    cudaGetSymbolAddress((void**)&pAgg, g_agg);
    __nv_bfloat16 *pW1h, *pW1l, *pW2h, *pW2l;
    cudaGetSymbolAddress((void**)&pW1h, g_W1T_hi);
    cudaGetSymbolAddress((void**)&pW1l, g_W1T_lo);
    cudaGetSymbolAddress((void**)&pW2h, g_W2T_hi);
    cudaGetSymbolAddress((void**)&pW2l, g_W2T_lo);

    const int SMEM_DYN = 4 * 128 * PADK * 2;   // 73728 B
    cudaFuncSetAttribute((const void*)gemm_fused<FEATK, false>,
                         cudaFuncAttributeMaxDynamicSharedMemorySize, SMEM_DYN);
    cudaFuncSetAttribute((const void*)gemm_fused<HID, true>,
                         cudaFuncAttributeMaxDynamicSharedMemorySize, SMEM_DYN);

    int ggrid = (M + 127) / 128;
    int cgrid = (HID * FEATK + HID * HID + 255) / 256;

    // one-time host resources for fork-join overlap (no device allocation)
    static cudaStream_t s2 = nullptr;
    static cudaEvent_t evF = nullptr, evJ = nullptr;
    if (s2 == nullptr) {
        cudaStreamCreateWithFlags(&s2, cudaStreamNonBlocking);
        cudaEventCreateWithFlags(&evF, cudaEventDisableTiming);
        cudaEventCreateWithFlags(&evJ, cudaEventDisableTiming);
    }

    // fork
    cudaEventRecord(evF, 0);
    cudaStreamWaitEvent(s2, evF, 0);

    // chain A (stream 0): convw -> prep -> gemm1
    convw_kernel<<<cgrid, 256>>>(W1, W2);                                   // #1
    prep_kernel<<<40, 256>>>(Ww, Wo, bw, bo);                               // #2
    // chain B (s2): zero -> scatter -> agg   (overlaps gemm1)
    zero_cnt_kernel<<<(NN + 255) / 256, 256, 0, s2>>>();                    // #3
    gemm_fused<FEATK, false><<<ggrid, 256, SMEM_DYN>>>(X, pW1h, pW1l, b1, out, M); // #4 <- profiled
    scatter_kernel<<<(E + 255) / 256, 256, 0, s2>>>(ei, E);                 // #5
    long long athreads = (long long)NN * 32;
    agg_kernel<<<(int)((athreads + 255) / 256), 256, 0, s2>>>(Wadj);        // #6

    // join: gemm2 needs agg (chain B) and out from gemm1 (chain A)
    cudaEventRecord(evJ, s2);
    cudaStreamWaitEvent(0, evJ, 0);
    gemm_fused<HID, true><<<ggrid, 256, SMEM_DYN>>>(pAgg, pW2h, pW2l, b2, out, M); // #7
}